// round 4
// baseline (speedup 1.0000x reference)
#include <cuda_runtime.h>
#include <cstdint>

// Unfold (im2col) — linear-output-sweep mapping.
// x: [16, 64, 112, 112] f32 ; out: [16, 576, 112, 112] f32
// out[n, c*9 + kh*3 + kw, h, w] = x[n, c, h+kh-1, w+kw-1] (0 outside)
//
// One warp = ONE output row (n, c, kk, h). Warps are ordered exactly in
// output linear order, so concurrent stores sweep DRAM densely (better
// page locality than the 9-plane fan-out). Input rows are re-read 9x but
// hit in L2 (51 MB resident). Lanes 0..27 hold 4 consecutive w as float4;
// kw=+/-1 shifts built from the aligned load via warp shuffle.

#define HWDIM 112
#define PLANE (HWDIM * HWDIM)   // 12544

__global__ __launch_bounds__(256) void unfold_kernel(
    const float* __restrict__ x, float* __restrict__ out)
{
    const int warp = (blockIdx.x * blockDim.x + threadIdx.x) >> 5;
    const int lane = threadIdx.x & 31;

    // warp -> (n, c, kk, h) in output linear order
    int h  = warp % HWDIM;
    int t  = warp / HWDIM;          // = ((n*64 + c)*9 + kk)
    int kk = t % 9;
    int nc = t / 9;                 // n*64 + c

    const int kh = kk / 3 - 1;      // -1,0,1
    const int kw = kk % 3 - 1;      // -1,0,1
    const int ih = h + kh;

    const bool wok = lane < 28;
    const int w0 = lane * 4;

    float4 cur = make_float4(0.f, 0.f, 0.f, 0.f);
    if (wok && (unsigned)ih < HWDIM)
        cur = *reinterpret_cast<const float4*>(
            x + (int64_t)nc * PLANE + ih * HWDIM + w0);

    float4 v;
    if (kw == 0) {
        v = cur;
    } else if (kw < 0) {
        float pw = __shfl_up_sync(0xFFFFFFFFu, cur.w, 1);
        if (lane == 0) pw = 0.f;                             // left pad
        v = make_float4(pw, cur.x, cur.y, cur.z);
    } else {
        float nx = __shfl_down_sync(0xFFFFFFFFu, cur.x, 1);  // lane27 gets 0
        v = make_float4(cur.y, cur.z, cur.w, nx);
    }

    if (wok)
        *reinterpret_cast<float4*>(
            out + ((int64_t)t * HWDIM + h) * HWDIM + w0) = v;
}

extern "C" void kernel_launch(void* const* d_in, const int* in_sizes, int n_in,
                              void* d_out, int out_size)
{
    const float* x = (const float*)d_in[0];
    float* out = (float*)d_out;

    const int warps = 16 * 64 * 9 * HWDIM;   // 1,032,192
    const int threads = 256;                 // 8 warps/block
    const int blocks = warps / 8;            // 129,024, exact
    unfold_kernel<<<blocks, threads>>>(x, out);
}

// round 5
// speedup vs baseline: 1.5556x; 1.5556x over previous
#include <cuda_runtime.h>
#include <cstdint>

// Unfold (im2col) — SMEM-staged tiles + TMA bulk stores.
// x: [16, 64, 112, 112] f32 ; out: [16, 576, 112, 112] f32
// out[n, c*9 + kh*3 + kw, h, w] = x[n, c, h+kh-1, w+kw-1] (0 outside)
//
// Block = (n, c, 8-row band). 8 warps: warp w owns row h0+w, loads rows
// h0+w-1..h0+w+1 as aligned float4 (L1/L2 hits across warps), builds the 9
// shifted variants via shfl, writes them to SMEM. Then cp.async.bulk pushes
// 9 chunks of 3584B (28 full 128B lines each, line-aligned) to GMEM via the
// TMA/bulk path — pure full-line streaming writes, no per-thread STG.

#define HWDIM 112
#define PLANE (HWDIM * HWDIM)   // 12544
#define ROWS  8
#define CHUNK_BYTES (ROWS * HWDIM * 4)   // 3584

__global__ __launch_bounds__(256) void unfold_kernel(
    const float* __restrict__ x, float* __restrict__ out)
{
    __shared__ __align__(16) float sm[9][ROWS][HWDIM];   // 31.5 KB

    const int blk = blockIdx.x;
    const int hb  = blk % (HWDIM / ROWS);   // 14 bands
    const int nc  = blk / (HWDIM / ROWS);   // n*64 + c
    const int h0  = hb * ROWS;

    const int wid  = threadIdx.x >> 5;      // 0..7 -> row h0+wid
    const int lane = threadIdx.x & 31;
    const int h    = h0 + wid;

    const bool wok = lane < 28;
    const int w0 = lane * 4;

    const float* plane = x + (int64_t)nc * PLANE;

    float4 r[3];
#pragma unroll
    for (int i = 0; i < 3; ++i) {
        const int ih = h - 1 + i;
        if (wok && (unsigned)ih < HWDIM)
            r[i] = *reinterpret_cast<const float4*>(plane + ih * HWDIM + w0);
        else
            r[i] = make_float4(0.f, 0.f, 0.f, 0.f);
    }

#pragma unroll
    for (int i = 0; i < 3; ++i) {
        float pw = __shfl_up_sync(0xFFFFFFFFu, r[i].w, 1);
        if (lane == 0) pw = 0.f;                               // left pad
        float nx = __shfl_down_sync(0xFFFFFFFFu, r[i].x, 1);   // lane27 gets 0
        if (wok) {
            *reinterpret_cast<float4*>(&sm[i * 3 + 0][wid][w0]) =
                make_float4(pw, r[i].x, r[i].y, r[i].z);        // kw = -1
            *reinterpret_cast<float4*>(&sm[i * 3 + 1][wid][w0]) = r[i];
            *reinterpret_cast<float4*>(&sm[i * 3 + 2][wid][w0]) =
                make_float4(r[i].y, r[i].z, r[i].w, nx);        // kw = +1
        }
    }

    __syncthreads();
    asm volatile("fence.proxy.async.shared::cta;" ::: "memory");

    // 9 bulk stores, one per kk-plane chunk (3584B contiguous, line-aligned)
    if (threadIdx.x < 9) {
        const int kk = threadIdx.x;
        uint32_t saddr;
        asm("{ .reg .u64 t; cvta.to.shared.u64 t, %1; cvt.u32.u64 %0, t; }"
            : "=r"(saddr) : "l"(&sm[kk][0][0]));
        float* gdst = out + ((int64_t)(nc * 9 + kk) * HWDIM + h0) * HWDIM;
        asm volatile(
            "cp.async.bulk.global.shared::cta.bulk_group [%0], [%1], %2;"
            :: "l"(gdst), "r"(saddr), "n"(CHUNK_BYTES) : "memory");
        asm volatile("cp.async.bulk.commit_group;" ::: "memory");
        asm volatile("cp.async.bulk.wait_group 0;" ::: "memory");
    }
}

extern "C" void kernel_launch(void* const* d_in, const int* in_sizes, int n_in,
                              void* d_out, int out_size)
{
    const float* x = (const float*)d_in[0];
    float* out = (float*)d_out;

    const int blocks = 16 * 64 * (HWDIM / ROWS);   // 14336
    unfold_kernel<<<blocks, 256>>>(x, out);
}